// round 12
// baseline (speedup 1.0000x reference)
#include <cuda_runtime.h>
#include <cstdint>

#define D_   256
#define Z_   32
#define B_   128
#define T_   1000
#define EPS_ 1e-6f
#define NOUT ((size_t)B_ * T_ * D_)
#define STH  320

typedef unsigned long long ull;

__device__ float g_z[(size_t)B_ * T_ * Z_];
__device__ float g_U[(size_t)B_ * T_ * D_];
__device__ float g_kl[64];

__device__ __forceinline__ float rcp_a(float x) {
    float r;
    asm("rcp.approx.f32 %0, %1;" : "=f"(r) : "f"(x));
    return r;
}
__device__ __forceinline__ float tanh_s(float x) {
    float ax = fabsf(x);
    float e = __expf(-2.0f * ax);
    return copysignf((1.0f - e) * rcp_a(1.0f + e), x);
}
__device__ __forceinline__ uint32_t smem_u32(const void* p) {
    uint32_t a;
    asm("{ .reg .u64 t; cvta.to.shared.u64 t, %1; cvt.u32.u64 %0, t; }" : "=r"(a) : "l"(p));
    return a;
}
__device__ __forceinline__ void ffma2(ull& acc, ull w, ull d) {
    asm("fma.rn.f32x2 %0, %1, %2, %0;" : "+l"(acc) : "l"(w), "l"(d));
}
__device__ __forceinline__ float unpack_sum(ull v) {
    float lo, hi;
    asm("mov.b64 {%0, %1}, %2;" : "=f"(lo), "=f"(hi) : "l"(v));
    return lo + hi;
}
__device__ __forceinline__ void unpack2(float& lo, float& hi, ull v) {
    asm("mov.b64 {%0, %1}, %2;" : "=f"(lo), "=f"(hi) : "l"(v));
}
__device__ __forceinline__ ull packf2(float lo, float hi) {
    ull v;
    asm("mov.b64 %0, {%1, %2};" : "=l"(v) : "f"(lo), "f"(hi));
    return v;
}
__device__ __forceinline__ void mbar_init(uint32_t addr, uint32_t cnt) {
    asm volatile("mbarrier.init.shared.b64 [%0], %1;" :: "r"(addr), "r"(cnt) : "memory");
}
__device__ __forceinline__ void mbar_arrive_peer(uint32_t peer_addr) {
    asm volatile("mbarrier.arrive.release.cluster.shared::cluster.b64 _, [%0];"
                 :: "r"(peer_addr) : "memory");
}
__device__ __forceinline__ void mbar_wait(uint32_t addr, uint32_t parity) {
    uint32_t done;
    asm volatile(
        "{\n\t.reg .pred p;\n\t"
        "mbarrier.try_wait.parity.acquire.cluster.shared::cta.b64 p, [%1], %2;\n\t"
        "selp.b32 %0, 1, 0, p;\n\t}"
        : "=r"(done) : "r"(addr), "r"(parity) : "memory");
    while (!done) {
        asm volatile(
            "{\n\t.reg .pred p;\n\t"
            "mbarrier.try_wait.parity.acquire.cluster.shared::cta.b64 p, [%1], %2, 0x989680;\n\t"
            "selp.b32 %0, 1, 0, p;\n\t}"
            : "=r"(done) : "r"(addr), "r"(parity) : "memory");
    }
}

// ---- z = tanh(A[:, :Z]) + noise * exp(A[:, Z:]) ----
__global__ __launch_bounds__(256) void z_kernel(const float* __restrict__ A,
                                                const float* __restrict__ nz) {
    int i = blockIdx.x * 256 + threadIdx.x;
    if (i >= B_ * T_ * Z_) return;
    int m = i >> 5, z = i & 31;
    g_z[i] = tanh_s(A[(size_t)m * 64 + z]) + nz[i] * __expf(A[(size_t)m * 64 + 32 + z]);
}

// ---- U = hd@Whd2h^T + z@Wz2h^T + bias : M=128000 N=256 K=288 ----
// FFMA2 inner loop. A tile stored DUPLICATED in smem so the broadcast operand
// (a,a) is one LDS.64; B pairs are contiguous LDS.128. acc packed over j.
__global__ __launch_bounds__(256, 1) void u_gemm(const float* __restrict__ hd,
                                                 const float* __restrict__ Wh,
                                                 const float* __restrict__ Wz,
                                                 const float* __restrict__ bias) {
    __shared__ float As2[2][8][256];   // duplicated pairs: [p][k][2m],[2m+1]
    __shared__ float Bs[2][8][128];
    int tid = threadIdx.x;
    int mB = blockIdx.y * 128, nB = blockIdx.x * 128;
    int lr = tid >> 1, lk = (tid & 1) << 2;
    int tr = (tid >> 4) << 3, tc = (tid & 15) << 3;
    ull acc2[8][4];                    // [i][jp] = (acc[i][2jp], acc[i][2jp+1])
#pragma unroll
    for (int i = 0; i < 8; i++)
#pragma unroll
        for (int jp = 0; jp < 4; jp++) acc2[i][jp] = 0ull;

    const float* aH = hd + (size_t)(mB + lr) * 256 + lk;
    const float* bH = Wh + (size_t)(nB + lr) * 256 + lk;
    const float* aZ = g_z + (size_t)(mB + lr) * 32 + lk;
    const float* bZ = Wz + (size_t)(nB + lr) * 32 + lk;

    {
        float4 av = *(const float4*)(aH);
        float4 bv = *(const float4*)(bH);
        ull* a2 = (ull*)&As2[0][lk][2 * lr];   // stride between k-rows = 256 floats
        a2[0]   = packf2(av.x, av.x);
        a2[128] = packf2(av.y, av.y);
        a2[256] = packf2(av.z, av.z);
        a2[384] = packf2(av.w, av.w);
        Bs[0][lk][lr] = bv.x; Bs[0][lk + 1][lr] = bv.y;
        Bs[0][lk + 2][lr] = bv.z; Bs[0][lk + 3][lr] = bv.w;
    }
    __syncthreads();

    int p = 0;
    for (int k0 = 0; k0 < 288; k0 += 8) {
        float4 nav, nbv;
        bool more = (k0 < 280);
        if (more) {
            int kn = k0 + 8;
            if (kn < 256) {
                nav = *(const float4*)(aH + kn);
                nbv = *(const float4*)(bH + kn);
            } else {
                nav = *(const float4*)(aZ + (kn - 256));
                nbv = *(const float4*)(bZ + (kn - 256));
            }
        }
#pragma unroll
        for (int kk = 0; kk < 8; kk++) {
            const ull* arow = (const ull*)&As2[p][kk][2 * tr];
            const ulonglong2* brow = (const ulonglong2*)&Bs[p][kk][tc];
            ulonglong2 nf01 = brow[0];   // (nf0,nf1),(nf2,nf3)
            ulonglong2 nf23 = brow[1];
#pragma unroll
            for (int i = 0; i < 8; i++) {
                ull mi = arow[i];
                ffma2(acc2[i][0], mi, nf01.x);
                ffma2(acc2[i][1], mi, nf01.y);
                ffma2(acc2[i][2], mi, nf23.x);
                ffma2(acc2[i][3], mi, nf23.y);
            }
        }
        if (more) {
            int q = p ^ 1;
            ull* a2 = (ull*)&As2[q][lk][2 * lr];
            a2[0]   = packf2(nav.x, nav.x);
            a2[128] = packf2(nav.y, nav.y);
            a2[256] = packf2(nav.z, nav.z);
            a2[384] = packf2(nav.w, nav.w);
            Bs[q][lk][lr] = nbv.x; Bs[q][lk + 1][lr] = nbv.y;
            Bs[q][lk + 2][lr] = nbv.z; Bs[q][lk + 3][lr] = nbv.w;
            p = q;
            __syncthreads();
        }
    }
    float bj[8];
#pragma unroll
    for (int j = 0; j < 8; j++) bj[j] = bias[nB + tc + j];
#pragma unroll
    for (int i = 0; i < 8; i++) {
        float* o = g_U + (size_t)(mB + tr + i) * 256 + nB + tc;
        float4 o0, o1;
        float x, y;
        unpack2(x, y, acc2[i][0]); o0.x = x + bj[0]; o0.y = y + bj[1];
        unpack2(x, y, acc2[i][1]); o0.z = x + bj[2]; o0.w = y + bj[3];
        unpack2(x, y, acc2[i][2]); o1.x = x + bj[4]; o1.y = y + bj[5];
        unpack2(x, y, acc2[i][3]); o1.z = x + bj[6]; o1.w = y + bj[7];
        *(float4*)(o)     = o0;
        *(float4*)(o + 4) = o1;
    }
}

// ---- wnll_init_h ----
__global__ __launch_bounds__(256) void wnll_kernel(const float* __restrict__ ih,
                                                   const float* __restrict__ mu,
                                                   float* __restrict__ out) {
    __shared__ float sr[8];
    int tid = threadIdx.x;
    float s = 0.f;
    for (int i = tid; i < B_ * D_; i += 256) {
        float d = ih[i] - mu[i & 255];
        s += 0.5f * d * d + 0.91893853320467274f;
    }
#pragma unroll
    for (int o = 16; o > 0; o >>= 1) s += __shfl_down_sync(~0u, s, o);
    if ((tid & 31) == 0) sr[tid >> 5] = s;
    __syncthreads();
    if (tid == 0) {
        float t = 0.f;
        for (int i = 0; i < 8; i++) t += sr[i];
        out[NOUT + 1] = 0.001f * t / 256.0f;
    }
}

// ---- kl final reduce ----
__global__ void kl_final(float* __restrict__ out) {
    if (threadIdx.x == 0) {
        float s = 0.f;
        for (int i = 0; i < 64; i++) s += g_kl[i];
        out[NOUT] = 0.001f / 32.0f * s;
    }
}

// one FMA k-slice (i is a compile-time literal at each expansion)
#define FMA_I(i) { \
    int kr = ks4 + 32 * (i); \
    ull d0a = *(const ull*)(dc + kr); \
    ull d0b = *(const ull*)(dc + kr + 2); \
    ull d1a = *(const ull*)(dc + 272 + kr); \
    ull d1b = *(const ull*)(dc + 272 + kr + 2); \
    _Pragma("unroll") \
    for (int j = 0; j < 4; j++) { \
        ffma2(acc[j][0], w2[i][0][j], d0a); \
        ffma2(acc[j][0], w2[i][1][j], d0b); \
        ffma2(acc[j][1], w2[i][0][j], d1a); \
        ffma2(acc[j][1], w2[i][1][j], d1b); \
    } }

// ---- sequential scan: reg weights + f32x2 FMA + split-k latency-hidden p2p sync ----
__global__ void __cluster_dims__(2, 1, 1) __launch_bounds__(STH, 1)
seq_kernel(const float* __restrict__ A, const float* __restrict__ in_p0,
           const float* __restrict__ Wd2h, const float* __restrict__ Wd2z,
           const float* __restrict__ initH, float* __restrict__ out) {
    __shared__ float dbuf[1088];              // [2 buf][2 b][272]
    __shared__ float dzs[256];                // [2 buf][2 b][64]
    __shared__ float sred[16];
    __shared__ __align__(8) ull mbar[2];      // full[buf], arrive count = 1

    const int tid = threadIdx.x;
    const int rank = blockIdx.x & 1;
    const int c = blockIdx.x >> 1;
    const int warp = tid >> 5, lane = tid & 31;
    const int j4sub = lane & 3, ks = lane >> 2;
    const int ks4 = ks * 4;
    const int jcol = (warp * 4 + j4sub) * 4;
    const int jsel = ((ks & 2) ? 2 : 0) + ((ks & 4) ? 1 : 0);
    const int jmine = jcol + jsel;
    const int bmine = ks & 1;
    const int ng = rank * 160 + jmine;
    const bool has_h = (ng < 256);
    const int b_u = 2 * c + bmine;
    const float dec  = (ng < 128) ? 0.75f : 0.5f;
    const float itau = (ng < 128) ? 0.25f : 0.5f;

    const bool isKL = (rank == 1) && (tid < 64);
    const int klb = tid >> 5, klz = tid & 31;
    float p0m = 0.f, p0s = 0.f, amu_p = 0.f, als_p = 0.f;
    const float* Ap = A + (size_t)(2 * c + klb) * T_ * 64;
    if (isKL) {
        p0m = in_p0[(2 * c + klb) * 64 + klz];
        p0s = in_p0[(2 * c + klb) * 64 + 32 + klz];
        amu_p = __ldg(Ap + klz);
        als_p = __ldg(Ap + 32 + klz);
    }

    // weights in registers as packed k-pairs (this CTA's 160 outputs)
    ull w2[8][2][4];
#pragma unroll
    for (int i = 0; i < 8; i++)
#pragma unroll
        for (int p = 0; p < 2; p++)
#pragma unroll
            for (int j = 0; j < 4; j++) {
                int n = rank * 160 + jcol + j;
                int k = ks4 + 32 * i + 2 * p;
                const float* src = (n < 256) ? (Wd2h + n * 256 + k)
                                             : (Wd2z + (n - 256) * 256 + k);
                w2[i][p][j] = packf2(__ldg(src), __ldg(src + 1));
            }

    // d0 = tanh(init_h), both batches, full 256 (local copy)
    for (int i = tid; i < 512; i += STH) {
        int bb = i >> 8, k = i & 255;
        dbuf[bb * 272 + k] = tanh_s(initH[(2 * c + bb) * 256 + k]);
    }
    float h = 0.f, u_pf = 0.f;
    const float* Up = g_U;
    float* Op = out;
    if (has_h) {
        h = initH[b_u * 256 + ng];
        Up = g_U + (size_t)b_u * T_ * 256 + ng;
        Op = out + (size_t)b_u * T_ * 256 + ng;
    }
    const uint32_t dl = smem_u32(dbuf);
    const uint32_t bl = smem_u32(mbar);
    uint32_t dp, bp;
    asm("mapa.shared::cluster.u32 %0, %1, %2;" : "=r"(dp) : "r"(dl), "r"(rank ^ 1));
    asm("mapa.shared::cluster.u32 %0, %1, %2;" : "=r"(bp) : "r"(bl), "r"(rank ^ 1));

    if (tid == 0) { mbar_init(bl, 1); mbar_init(bl + 8, 1); }
    __syncthreads();
    asm volatile("barrier.cluster.arrive.aligned;\n\tbarrier.cluster.wait.aligned;" ::: "memory");

    if (has_h) u_pf = __ldg(Up);

    float klacc = 0.f;
    uint32_t ph0 = 0, ph1 = 0;
    int cur = 0;
    for (int t = 0; t < T_; ++t) {
        const float* dc = dbuf + cur * 544;
        ull acc[4][2];
#pragma unroll
        for (int j = 0; j < 4; j++) { acc[j][0] = 0ull; acc[j][1] = 0ull; }

        // ---- local-k FMA first (hides the wait), then wait, then peer-k ----
        if (rank == 0) {
            FMA_I(0) FMA_I(1) FMA_I(2) FMA_I(3) FMA_I(4)
            if (t > 0) {
                if (cur) { mbar_wait(bl + 8, ph1); ph1 ^= 1; }
                else     { mbar_wait(bl,     ph0); ph0 ^= 1; }
            }
            FMA_I(5) FMA_I(6) FMA_I(7)
        } else {
            FMA_I(5) FMA_I(6) FMA_I(7)
            if (t > 0) {
                if (cur) { mbar_wait(bl + 8, ph1); ph1 ^= 1; }
                else     { mbar_wait(bl,     ph0); ph0 ^= 1; }
            }
            FMA_I(0) FMA_I(1) FMA_I(2) FMA_I(3) FMA_I(4)
        }

        float4 a0 = make_float4(unpack_sum(acc[0][0]), unpack_sum(acc[1][0]),
                                unpack_sum(acc[2][0]), unpack_sum(acc[3][0]));
        float4 a1 = make_float4(unpack_sum(acc[0][1]), unpack_sum(acc[1][1]),
                                unpack_sum(acc[2][1]), unpack_sum(acc[3][1]));

        // butterfly reduce over ks (lane bits 2,3,4), halving payload
        float4 keep, send;
        if (bmine) { keep = a1; send = a0; } else { keep = a0; send = a1; }
        keep.x += __shfl_xor_sync(~0u, send.x, 4);
        keep.y += __shfl_xor_sync(~0u, send.y, 4);
        keep.z += __shfl_xor_sync(~0u, send.z, 4);
        keep.w += __shfl_xor_sync(~0u, send.w, 4);
        float k2x, k2y, s2x, s2y;
        if (ks & 2) { k2x = keep.z; k2y = keep.w; s2x = keep.x; s2y = keep.y; }
        else        { k2x = keep.x; k2y = keep.y; s2x = keep.z; s2y = keep.w; }
        k2x += __shfl_xor_sync(~0u, s2x, 8);
        k2y += __shfl_xor_sync(~0u, s2y, 8);
        float k3, s3;
        if (ks & 4) { k3 = k2y; s3 = k2x; } else { k3 = k2x; s3 = k2y; }
        float f = k3 + __shfl_xor_sync(~0u, s3, 16);

        int nxt = cur ^ 1;
        if (has_h) {
            h = dec * h + itau * (f + u_pf);
            float dn = tanh_s(h);
            int off = nxt * 544 + bmine * 272 + ng;
            dbuf[off] = dn;                        // local copy
            asm volatile("st.shared::cluster.b32 [%0], %1;"
                         :: "r"(dp + (uint32_t)(off * 4)),
                            "r"(__float_as_uint(dn)) : "memory");
            *Op = dn;
            Op += 256;
        } else {
            dzs[(t & 1) * 128 + bmine * 64 + (jmine - 96)] = f;
        }

        __syncthreads();                           // local d(t+1)/dz(t) ordered
        if (tid == 0)
            mbar_arrive_peer(bp + (uint32_t)(nxt * 8));   // signal peer: d(t+1) half delivered

        // same-step KL (dzs local on rank 1)
        if (isKL) {
            float mq = tanh_s(amu_p), sq = __expf(als_p);
            float pm, ps;
            if (t == 0) { pm = p0m; ps = p0s; }
            else {
                const float* dzp = dzs + (t & 1) * 128 + klb * 64;
                pm = dzp[klz]; ps = dzp[32 + klz];
            }
            float mp = tanh_s(pm), sp = __expf(ps);
            float dm = mq - mp;
            klacc += __logf(sp + EPS_) - __logf(sq + EPS_) - 0.5f
                   + 0.5f * (dm * dm + sq * sq) / (sp * sp + EPS_);
            Ap += 64;
            if (t + 1 < T_) {
                amu_p = __ldg(Ap + klz);
                als_p = __ldg(Ap + 32 + klz);
            }
        }

        if (has_h && t + 1 < T_) {
            Up += 256;
            u_pf = __ldg(Up);
        }
        cur = nxt;
    }

    if (rank == 1) {
        float v = (tid < 64) ? klacc : 0.f;
#pragma unroll
        for (int o = 16; o > 0; o >>= 1) v += __shfl_down_sync(~0u, v, o);
        if (lane == 0) sred[warp] = v;
        __syncthreads();
        if (tid == 0) {
            float s = 0.f;
            for (int w = 0; w < 10; w++) s += sred[w];
            g_kl[c] = s;
        }
    }
    // no CTA may exit while peer DSMEM traffic is in flight
    asm volatile("barrier.cluster.arrive.aligned;\n\tbarrier.cluster.wait.aligned;" ::: "memory");
}

extern "C" void kernel_launch(void* const* d_in, const int* in_sizes, int n_in,
                              void* d_out, int out_size) {
    const float* hd    = (const float*)d_in[0];
    const float* A     = (const float*)d_in[1];
    const float* in_p0 = (const float*)d_in[2];
    const float* noise = (const float*)d_in[3];
    const float* Wd2h  = (const float*)d_in[4];
    const float* Wz2h  = (const float*)d_in[5];
    const float* Wd2z  = (const float*)d_in[6];
    const float* Whd2h = (const float*)d_in[7];
    const float* biasd = (const float*)d_in[8];
    const float* initH = (const float*)d_in[9];
    const float* ihmu  = (const float*)d_in[10];
    float* out = (float*)d_out;

    z_kernel<<<(B_ * T_ * Z_ + 255) / 256, 256>>>(A, noise);
    u_gemm<<<dim3(2, 1000), 256>>>(hd, Whd2h, Wz2h, biasd);
    wnll_kernel<<<1, 256>>>(initH, ihmu, out);

    seq_kernel<<<128, STH>>>(A, in_p0, Wd2h, Wd2z, initH, out);
    kl_final<<<1, 32>>>(out);
}

// round 15
// speedup vs baseline: 1.2163x; 1.2163x over previous
#include <cuda_runtime.h>
#include <cstdint>

#define D_   256
#define Z_   32
#define B_   128
#define T_   1000
#define EPS_ 1e-6f
#define NOUT ((size_t)B_ * T_ * D_)
#define STH  320

typedef unsigned long long ull;

__device__ float g_z[(size_t)B_ * T_ * Z_];
__device__ float g_U[(size_t)B_ * T_ * D_];
__device__ float g_kl[64];

__device__ __forceinline__ float rcp_a(float x) {
    float r;
    asm("rcp.approx.f32 %0, %1;" : "=f"(r) : "f"(x));
    return r;
}
__device__ __forceinline__ float tanh_s(float x) {
    float ax = fabsf(x);
    float e = __expf(-2.0f * ax);
    return copysignf((1.0f - e) * rcp_a(1.0f + e), x);
}
__device__ __forceinline__ uint32_t smem_u32(const void* p) {
    uint32_t a;
    asm("{ .reg .u64 t; cvta.to.shared.u64 t, %1; cvt.u32.u64 %0, t; }" : "=r"(a) : "l"(p));
    return a;
}
__device__ __forceinline__ void ffma2(ull& acc, ull w, ull d) {
    asm("fma.rn.f32x2 %0, %1, %2, %0;" : "+l"(acc) : "l"(w), "l"(d));
}
__device__ __forceinline__ float unpack_sum(ull v) {
    float lo, hi;
    asm("mov.b64 {%0, %1}, %2;" : "=f"(lo), "=f"(hi) : "l"(v));
    return lo + hi;
}
__device__ __forceinline__ ull packf2(float lo, float hi) {
    ull v;
    asm("mov.b64 %0, {%1, %2};" : "=l"(v) : "f"(lo), "f"(hi));
    return v;
}
__device__ __forceinline__ uint32_t to_tf32(float x) {
    uint32_t r;
    asm("cvt.rna.tf32.f32 %0, %1;" : "=r"(r) : "f"(x));
    return r;
}
__device__ __forceinline__ void mma_tf32(float* c, uint32_t a0, uint32_t a1,
                                         uint32_t a2, uint32_t a3,
                                         uint32_t b0, uint32_t b1) {
    asm("mma.sync.aligned.m16n8k8.row.col.f32.tf32.tf32.f32 "
        "{%0,%1,%2,%3}, {%4,%5,%6,%7}, {%8,%9}, {%0,%1,%2,%3};"
        : "+f"(c[0]), "+f"(c[1]), "+f"(c[2]), "+f"(c[3])
        : "r"(a0), "r"(a1), "r"(a2), "r"(a3), "r"(b0), "r"(b1));
}
__device__ __forceinline__ void mbar_init(uint32_t addr, uint32_t cnt) {
    asm volatile("mbarrier.init.shared.b64 [%0], %1;" :: "r"(addr), "r"(cnt) : "memory");
}
__device__ __forceinline__ void mbar_arrive_peer(uint32_t peer_addr) {
    asm volatile("mbarrier.arrive.release.cluster.shared::cluster.b64 _, [%0];"
                 :: "r"(peer_addr) : "memory");
}
__device__ __forceinline__ void mbar_wait(uint32_t addr, uint32_t parity) {
    uint32_t done;
    asm volatile(
        "{\n\t.reg .pred p;\n\t"
        "mbarrier.try_wait.parity.acquire.cluster.shared::cta.b64 p, [%1], %2;\n\t"
        "selp.b32 %0, 1, 0, p;\n\t}"
        : "=r"(done) : "r"(addr), "r"(parity) : "memory");
    while (!done) {
        asm volatile(
            "{\n\t.reg .pred p;\n\t"
            "mbarrier.try_wait.parity.acquire.cluster.shared::cta.b64 p, [%1], %2, 0x989680;\n\t"
            "selp.b32 %0, 1, 0, p;\n\t}"
            : "=r"(done) : "r"(addr), "r"(parity) : "memory");
    }
}

// ---- z = tanh(A[:, :Z]) + noise * exp(A[:, Z:]) ----
__global__ __launch_bounds__(256) void z_kernel(const float* __restrict__ A,
                                                const float* __restrict__ nz) {
    int i = blockIdx.x * 256 + threadIdx.x;
    if (i >= B_ * T_ * Z_) return;
    int m = i >> 5, z = i & 31;
    g_z[i] = tanh_s(A[(size_t)m * 64 + z]) + nz[i] * __expf(A[(size_t)m * 64 + 32 + z]);
}

// ---- U = hd@Whd2h^T + z@Wz2h^T + bias : tf32 tensor cores ----
// M=128000 N=256 K=288. Block tile 128x128xk8, 8 warps (warp tile 32x64).
// smem stride 136 => all fragment LDS.32 loads are bank-conflict-free.
__global__ __launch_bounds__(256, 2) void u_gemm(const float* __restrict__ hd,
                                                 const float* __restrict__ Wh,
                                                 const float* __restrict__ Wz,
                                                 const float* __restrict__ bias) {
    __shared__ uint32_t As[2][8][136];   // [k][m], tf32 bits
    __shared__ uint32_t Bs[2][8][136];   // [k][n], tf32 bits
    const int tid = threadIdx.x;
    const int warp = tid >> 5, lane = tid & 31;
    const int mB = blockIdx.y * 128, nB = blockIdx.x * 128;
    const int lr = tid & 127;            // row within tile
    const int lk = (tid >> 7) << 2;      // k 0..3 or 4..7
    const int wm = warp >> 1;            // 0..3 -> m offset wm*32
    const int wn = warp & 1;             // 0..1 -> n offset wn*64
    const int grp = lane >> 2, tig = lane & 3;

    float acc[16][4];                    // [mt*8+nt][c0..c3]
#pragma unroll
    for (int i = 0; i < 16; i++)
#pragma unroll
        for (int j = 0; j < 4; j++) acc[i][j] = 0.f;

    const float* aH = hd + (size_t)(mB + lr) * 256 + lk;
    const float* bH = Wh + (size_t)(nB + lr) * 256 + lk;
    const float* aZ = g_z + (size_t)(mB + lr) * 32 + lk;
    const float* bZ = Wz + (size_t)(nB + lr) * 32 + lk;

    {
        float4 av = *(const float4*)(aH);
        float4 bv = *(const float4*)(bH);
        As[0][lk][lr] = to_tf32(av.x); As[0][lk + 1][lr] = to_tf32(av.y);
        As[0][lk + 2][lr] = to_tf32(av.z); As[0][lk + 3][lr] = to_tf32(av.w);
        Bs[0][lk][lr] = to_tf32(bv.x); Bs[0][lk + 1][lr] = to_tf32(bv.y);
        Bs[0][lk + 2][lr] = to_tf32(bv.z); Bs[0][lk + 3][lr] = to_tf32(bv.w);
    }
    __syncthreads();

    int p = 0;
    for (int k0 = 0; k0 < 288; k0 += 8) {
        float4 nav, nbv;
        bool more = (k0 < 280);
        if (more) {
            int kn = k0 + 8;
            if (kn < 256) {
                nav = *(const float4*)(aH + kn);
                nbv = *(const float4*)(bH + kn);
            } else {
                nav = *(const float4*)(aZ + (kn - 256));
                nbv = *(const float4*)(bZ + (kn - 256));
            }
        }
        // B fragments for this warp's 8 n-tiles
        uint32_t bf0[8], bf1[8];
#pragma unroll
        for (int nt = 0; nt < 8; nt++) {
            int n = wn * 64 + nt * 8 + grp;
            bf0[nt] = Bs[p][tig][n];
            bf1[nt] = Bs[p][tig + 4][n];
        }
#pragma unroll
        for (int mt = 0; mt < 2; mt++) {
            int m = wm * 32 + mt * 16 + grp;
            uint32_t a0 = As[p][tig][m];
            uint32_t a1 = As[p][tig][m + 8];
            uint32_t a2 = As[p][tig + 4][m];
            uint32_t a3 = As[p][tig + 4][m + 8];
#pragma unroll
            for (int nt = 0; nt < 8; nt++)
                mma_tf32(acc[mt * 8 + nt], a0, a1, a2, a3, bf0[nt], bf1[nt]);
        }
        if (more) {
            int q = p ^ 1;
            As[q][lk][lr] = to_tf32(nav.x); As[q][lk + 1][lr] = to_tf32(nav.y);
            As[q][lk + 2][lr] = to_tf32(nav.z); As[q][lk + 3][lr] = to_tf32(nav.w);
            Bs[q][lk][lr] = to_tf32(nbv.x); Bs[q][lk + 1][lr] = to_tf32(nbv.y);
            Bs[q][lk + 2][lr] = to_tf32(nbv.z); Bs[q][lk + 3][lr] = to_tf32(nbv.w);
            p = q;
            __syncthreads();
        }
    }

    // epilogue: c0,c1 at (row, 2tig..+1); c2,c3 at (row+8, same cols)
#pragma unroll
    for (int nt = 0; nt < 8; nt++) {
        int cb = nB + wn * 64 + nt * 8 + 2 * tig;
        float bj0 = bias[cb], bj1 = bias[cb + 1];
#pragma unroll
        for (int mt = 0; mt < 2; mt++) {
            int rb = mB + wm * 32 + mt * 16 + grp;
            float* o0 = g_U + (size_t)rb * 256 + cb;
            float* o1 = g_U + (size_t)(rb + 8) * 256 + cb;
            float2 v0 = make_float2(acc[mt * 8 + nt][0] + bj0, acc[mt * 8 + nt][1] + bj1);
            float2 v1 = make_float2(acc[mt * 8 + nt][2] + bj0, acc[mt * 8 + nt][3] + bj1);
            *(float2*)o0 = v0;
            *(float2*)o1 = v1;
        }
    }
}

// ---- wnll_init_h ----
__global__ __launch_bounds__(256) void wnll_kernel(const float* __restrict__ ih,
                                                   const float* __restrict__ mu,
                                                   float* __restrict__ out) {
    __shared__ float sr[8];
    int tid = threadIdx.x;
    float s = 0.f;
    for (int i = tid; i < B_ * D_; i += 256) {
        float d = ih[i] - mu[i & 255];
        s += 0.5f * d * d + 0.91893853320467274f;
    }
#pragma unroll
    for (int o = 16; o > 0; o >>= 1) s += __shfl_down_sync(~0u, s, o);
    if ((tid & 31) == 0) sr[tid >> 5] = s;
    __syncthreads();
    if (tid == 0) {
        float t = 0.f;
        for (int i = 0; i < 8; i++) t += sr[i];
        out[NOUT + 1] = 0.001f * t / 256.0f;
    }
}

// ---- kl final reduce ----
__global__ void kl_final(float* __restrict__ out) {
    if (threadIdx.x == 0) {
        float s = 0.f;
        for (int i = 0; i < 64; i++) s += g_kl[i];
        out[NOUT] = 0.001f / 32.0f * s;
    }
}

// one FMA k-slice (i is a compile-time literal at each expansion)
#define FMA_I(i) { \
    int kr = ks4 + 32 * (i); \
    ull d0a = *(const ull*)(dc + kr); \
    ull d0b = *(const ull*)(dc + kr + 2); \
    ull d1a = *(const ull*)(dc + 272 + kr); \
    ull d1b = *(const ull*)(dc + 272 + kr + 2); \
    _Pragma("unroll") \
    for (int j = 0; j < 4; j++) { \
        ffma2(acc[j][0], w2[i][0][j], d0a); \
        ffma2(acc[j][0], w2[i][1][j], d0b); \
        ffma2(acc[j][1], w2[i][0][j], d1a); \
        ffma2(acc[j][1], w2[i][1][j], d1b); \
    } }

// ---- sequential scan: reg weights + f32x2 FMA + split-k latency-hidden p2p sync ----
__global__ void __cluster_dims__(2, 1, 1) __launch_bounds__(STH, 1)
seq_kernel(const float* __restrict__ A, const float* __restrict__ in_p0,
           const float* __restrict__ Wd2h, const float* __restrict__ Wd2z,
           const float* __restrict__ initH, float* __restrict__ out) {
    __shared__ float dbuf[1088];              // [2 buf][2 b][272]
    __shared__ float dzs[256];                // [2 buf][2 b][64]
    __shared__ float sred[16];
    __shared__ __align__(8) ull mbar[2];      // full[buf], arrive count = 1

    const int tid = threadIdx.x;
    const int rank = blockIdx.x & 1;
    const int c = blockIdx.x >> 1;
    const int warp = tid >> 5, lane = tid & 31;
    const int j4sub = lane & 3, ks = lane >> 2;
    const int ks4 = ks * 4;
    const int jcol = (warp * 4 + j4sub) * 4;
    const int jsel = ((ks & 2) ? 2 : 0) + ((ks & 4) ? 1 : 0);
    const int jmine = jcol + jsel;
    const int bmine = ks & 1;
    const int ng = rank * 160 + jmine;
    const bool has_h = (ng < 256);
    const int b_u = 2 * c + bmine;
    const float dec  = (ng < 128) ? 0.75f : 0.5f;
    const float itau = (ng < 128) ? 0.25f : 0.5f;

    const bool isKL = (rank == 1) && (tid < 64);
    const int klb = tid >> 5, klz = tid & 31;
    float p0m = 0.f, p0s = 0.f, amu_p = 0.f, als_p = 0.f;
    const float* Ap = A + (size_t)(2 * c + klb) * T_ * 64;
    if (isKL) {
        p0m = in_p0[(2 * c + klb) * 64 + klz];
        p0s = in_p0[(2 * c + klb) * 64 + 32 + klz];
        amu_p = __ldg(Ap + klz);
        als_p = __ldg(Ap + 32 + klz);
    }

    // weights in registers as packed k-pairs (this CTA's 160 outputs)
    ull w2[8][2][4];
#pragma unroll
    for (int i = 0; i < 8; i++)
#pragma unroll
        for (int p = 0; p < 2; p++)
#pragma unroll
            for (int j = 0; j < 4; j++) {
                int n = rank * 160 + jcol + j;
                int k = ks4 + 32 * i + 2 * p;
                const float* src = (n < 256) ? (Wd2h + n * 256 + k)
                                             : (Wd2z + (n - 256) * 256 + k);
                w2[i][p][j] = packf2(__ldg(src), __ldg(src + 1));
            }

    // d0 = tanh(init_h), both batches, full 256 (local copy)
    for (int i = tid; i < 512; i += STH) {
        int bb = i >> 8, k = i & 255;
        dbuf[bb * 272 + k] = tanh_s(initH[(2 * c + bb) * 256 + k]);
    }
    float h = 0.f, u_pf = 0.f;
    const float* Up = g_U;
    float* Op = out;
    if (has_h) {
        h = initH[b_u * 256 + ng];
        Up = g_U + (size_t)b_u * T_ * 256 + ng;
        Op = out + (size_t)b_u * T_ * 256 + ng;
    }
    const uint32_t dl = smem_u32(dbuf);
    const uint32_t bl = smem_u32(mbar);
    uint32_t dp, bp;
    asm("mapa.shared::cluster.u32 %0, %1, %2;" : "=r"(dp) : "r"(dl), "r"(rank ^ 1));
    asm("mapa.shared::cluster.u32 %0, %1, %2;" : "=r"(bp) : "r"(bl), "r"(rank ^ 1));

    if (tid == 0) { mbar_init(bl, 1); mbar_init(bl + 8, 1); }
    __syncthreads();
    asm volatile("barrier.cluster.arrive.aligned;\n\tbarrier.cluster.wait.aligned;" ::: "memory");

    if (has_h) u_pf = __ldg(Up);

    float klacc = 0.f;
    uint32_t ph0 = 0, ph1 = 0;
    int cur = 0;
    for (int t = 0; t < T_; ++t) {
        const float* dc = dbuf + cur * 544;
        ull acc[4][2];
#pragma unroll
        for (int j = 0; j < 4; j++) { acc[j][0] = 0ull; acc[j][1] = 0ull; }

        // ---- local-k FMA first (hides the wait), then wait, then peer-k ----
        if (rank == 0) {
            FMA_I(0) FMA_I(1) FMA_I(2) FMA_I(3) FMA_I(4)
            if (t > 0) {
                if (cur) { mbar_wait(bl + 8, ph1); ph1 ^= 1; }
                else     { mbar_wait(bl,     ph0); ph0 ^= 1; }
            }
            FMA_I(5) FMA_I(6) FMA_I(7)
        } else {
            FMA_I(5) FMA_I(6) FMA_I(7)
            if (t > 0) {
                if (cur) { mbar_wait(bl + 8, ph1); ph1 ^= 1; }
                else     { mbar_wait(bl,     ph0); ph0 ^= 1; }
            }
            FMA_I(0) FMA_I(1) FMA_I(2) FMA_I(3) FMA_I(4)
        }

        float4 a0 = make_float4(unpack_sum(acc[0][0]), unpack_sum(acc[1][0]),
                                unpack_sum(acc[2][0]), unpack_sum(acc[3][0]));
        float4 a1 = make_float4(unpack_sum(acc[0][1]), unpack_sum(acc[1][1]),
                                unpack_sum(acc[2][1]), unpack_sum(acc[3][1]));

        // butterfly reduce over ks (lane bits 2,3,4), halving payload
        float4 keep, send;
        if (bmine) { keep = a1; send = a0; } else { keep = a0; send = a1; }
        keep.x += __shfl_xor_sync(~0u, send.x, 4);
        keep.y += __shfl_xor_sync(~0u, send.y, 4);
        keep.z += __shfl_xor_sync(~0u, send.z, 4);
        keep.w += __shfl_xor_sync(~0u, send.w, 4);
        float k2x, k2y, s2x, s2y;
        if (ks & 2) { k2x = keep.z; k2y = keep.w; s2x = keep.x; s2y = keep.y; }
        else        { k2x = keep.x; k2y = keep.y; s2x = keep.z; s2y = keep.w; }
        k2x += __shfl_xor_sync(~0u, s2x, 8);
        k2y += __shfl_xor_sync(~0u, s2y, 8);
        float k3, s3;
        if (ks & 4) { k3 = k2y; s3 = k2x; } else { k3 = k2x; s3 = k2y; }
        float f = k3 + __shfl_xor_sync(~0u, s3, 16);

        int nxt = cur ^ 1;
        if (has_h) {
            h = dec * h + itau * (f + u_pf);
            float dn = tanh_s(h);
            int off = nxt * 544 + bmine * 272 + ng;
            dbuf[off] = dn;                        // local copy
            asm volatile("st.shared::cluster.b32 [%0], %1;"
                         :: "r"(dp + (uint32_t)(off * 4)),
                            "r"(__float_as_uint(dn)) : "memory");
            *Op = dn;
            Op += 256;
        } else {
            dzs[(t & 1) * 128 + bmine * 64 + (jmine - 96)] = f;
        }

        __syncthreads();                           // local d(t+1)/dz(t) ordered
        if (tid == 0)
            mbar_arrive_peer(bp + (uint32_t)(nxt * 8));   // signal peer: d(t+1) half delivered

        // same-step KL (dzs local on rank 1)
        if (isKL) {
            float mq = tanh_s(amu_p), sq = __expf(als_p);
            float pm, ps;
            if (t == 0) { pm = p0m; ps = p0s; }
            else {
                const float* dzp = dzs + (t & 1) * 128 + klb * 64;
                pm = dzp[klz]; ps = dzp[32 + klz];
            }
            float mp = tanh_s(pm), sp = __expf(ps);
            float dm = mq - mp;
            klacc += __logf(sp + EPS_) - __logf(sq + EPS_) - 0.5f
                   + 0.5f * (dm * dm + sq * sq) / (sp * sp + EPS_);
            Ap += 64;
            if (t + 1 < T_) {
                amu_p = __ldg(Ap + klz);
                als_p = __ldg(Ap + 32 + klz);
            }
        }

        if (has_h && t + 1 < T_) {
            Up += 256;
            u_pf = __ldg(Up);
        }
        cur = nxt;
    }

    if (rank == 1) {
        float v = (tid < 64) ? klacc : 0.f;
#pragma unroll
        for (int o = 16; o > 0; o >>= 1) v += __shfl_down_sync(~0u, v, o);
        if (lane == 0) sred[warp] = v;
        __syncthreads();
        if (tid == 0) {
            float s = 0.f;
            for (int w = 0; w < 10; w++) s += sred[w];
            g_kl[c] = s;
        }
    }
    // no CTA may exit while peer DSMEM traffic is in flight
    asm volatile("barrier.cluster.arrive.aligned;\n\tbarrier.cluster.wait.aligned;" ::: "memory");
}

extern "C" void kernel_launch(void* const* d_in, const int* in_sizes, int n_in,
                              void* d_out, int out_size) {
    const float* hd    = (const float*)d_in[0];
    const float* A     = (const float*)d_in[1];
    const float* in_p0 = (const float*)d_in[2];
    const float* noise = (const float*)d_in[3];
    const float* Wd2h  = (const float*)d_in[4];
    const float* Wz2h  = (const float*)d_in[5];
    const float* Wd2z  = (const float*)d_in[6];
    const float* Whd2h = (const float*)d_in[7];
    const float* biasd = (const float*)d_in[8];
    const float* initH = (const float*)d_in[9];
    const float* ihmu  = (const float*)d_in[10];
    float* out = (float*)d_out;

    z_kernel<<<(B_ * T_ * Z_ + 255) / 256, 256>>>(A, noise);
    u_gemm<<<dim3(2, 1000), 256>>>(hd, Whd2h, Wz2h, biasd);
    wnll_kernel<<<1, 256>>>(initH, ihmu, out);

    seq_kernel<<<128, STH>>>(A, in_p0, Wd2h, Wd2z, initH, out);
    kl_final<<<1, 32>>>(out);
}